// round 13
// baseline (speedup 1.0000x reference)
#include <cuda_runtime.h>
#include <cuda_fp16.h>
#include <cstdint>

#define BATCH 64
#define NOBJ  64
#define HID   256
#define OUTC  28
#define NTILES 2048
#define GRID_PAIR 148

__device__ float g_U[BATCH * NOBJ * HID];
__device__ float g_V[BATCH * NOBJ * HID];
__device__ float g_PART[BATCH * NOBJ * HID];
// Packed weights (fp16): 6 chunks (3 layers x 2 k-halves), each 64KB
// = [128 k-rows x 256 n] fp16, swizzled: phys_byte = r*512 + ((n*2) ^ ((r&7)<<4))
__device__ __align__(128) __half g_Wpack[6 * 32768];

// ---------------- PTX helpers (sm_90-portable only) ----------------
__device__ __forceinline__ uint32_t smem_u32(const void* p) {
    uint32_t a;
    asm("{ .reg .u64 t; cvta.to.shared.u64 t, %1; cvt.u32.u64 %0, t; }" : "=r"(a) : "l"(p));
    return a;
}
#define MBAR_INIT(addr, cnt) \
    asm volatile("mbarrier.init.shared.b64 [%0], %1;" :: "r"(addr), "r"((uint32_t)(cnt)) : "memory")
#define MBAR_EXPECT_TX(addr, n) \
    asm volatile("mbarrier.arrive.expect_tx.shared.b64 _, [%0], %1;" :: "r"(addr), "r"((uint32_t)(n)) : "memory")
#define MBAR_ARRIVE(addr) \
    asm volatile("mbarrier.arrive.shared.b64 _, [%0];" :: "r"(addr) : "memory")

__device__ __forceinline__ void mbar_wait(uint32_t mbar, uint32_t parity) {
    asm volatile(
        "{\n\t.reg .pred P1;\n\t"
        "WL_%=:\n\t"
        "mbarrier.try_wait.parity.acquire.cta.shared::cta.b64 P1, [%0], %1, 0x989680;\n\t"
        "@P1 bra.uni WD_%=;\n\t"
        "bra.uni WL_%=;\n\t"
        "WD_%=:\n\t}"
        :: "r"(mbar), "r"(parity) : "memory");
}
__device__ __forceinline__ void bulk_g2s(uint32_t dst, const void* src,
                                         uint32_t bytes, uint32_t mbar) {
    asm volatile(
        "cp.async.bulk.shared::cluster.global.mbarrier::complete_tx::bytes [%0], [%1], %2, [%3];"
        :: "r"(dst), "l"(src), "r"(bytes), "r"(mbar) : "memory");
}

#define LDSM_X4(r0, r1, r2, r3, addr) \
    asm volatile("ldmatrix.sync.aligned.m8n8.x4.shared.b16 {%0,%1,%2,%3}, [%4];" \
                 : "=r"(r0), "=r"(r1), "=r"(r2), "=r"(r3) : "r"(addr))
#define LDSM_X4_T(r0, r1, r2, r3, addr) \
    asm volatile("ldmatrix.sync.aligned.m8n8.x4.trans.shared.b16 {%0,%1,%2,%3}, [%4];" \
                 : "=r"(r0), "=r"(r1), "=r"(r2), "=r"(r3) : "r"(addr))

__device__ __forceinline__ void mma16816(float* c, const uint32_t* a, const uint32_t* b) {
    asm volatile(
        "mma.sync.aligned.m16n8k16.row.col.f32.f16.f16.f32 "
        "{%0,%1,%2,%3}, {%4,%5,%6,%7}, {%8,%9}, {%0,%1,%2,%3};"
        : "+f"(c[0]), "+f"(c[1]), "+f"(c[2]), "+f"(c[3])
        : "r"(a[0]), "r"(a[1]), "r"(a[2]), "r"(a[3]), "r"(b[0]), "r"(b[1]));
}

__device__ __forceinline__ uint32_t h2_bits(__half2 h) {
    return *reinterpret_cast<uint32_t*>(&h);
}

// ---------------- Kernel 1: U, V (g1 split by linearity; qst hoisted) --------
__global__ void prep_kernel(const float* __restrict__ x, const float* __restrict__ qst,
                            const float* __restrict__ g1_w, const float* __restrict__ g1_b) {
    __shared__ float sxf[26][16];
    __shared__ float sq[128];
    const int b = blockIdx.y, j0 = blockIdx.x * 16, t = threadIdx.x;

    for (int i = t; i < 24 * 16; i += 256) {
        int k = i >> 4, j = i & 15;
        sxf[k][j] = x[(b * 24 + k) * 64 + j0 + j];
    }
    if (t < 16) sxf[24][t] = ((float)(j0 + t) * 0.125f - 4.0f) * 0.25f;
    else if (t < 32) {
        int j = t - 16;
        sxf[25][j] = ((float)((j0 + j) & 7) - 4.0f) * 0.25f;
    }
    if (t >= 128) sq[t - 128] = qst[b * 128 + (t - 128)];
    __syncthreads();

    float vq = g1_b[t];
#pragma unroll 8
    for (int q = 0; q < 128; q++) vq += sq[q] * g1_w[(52 + q) * HID + t];

    float u[16], v[16];
#pragma unroll
    for (int j = 0; j < 16; j++) { u[j] = 0.f; v[j] = 0.f; }
#pragma unroll
    for (int p = 0; p < 26; p++) {
        float wu = g1_w[p * HID + t];
        float wv = g1_w[(26 + p) * HID + t];
#pragma unroll
        for (int j = 0; j < 16; j++) {
            float s = sxf[p][j];
            u[j] += s * wu;
            v[j] += s * wv;
        }
    }
#pragma unroll
    for (int j = 0; j < 16; j++) {
        g_U[(b * NOBJ + j0 + j) * HID + t] = u[j];
        g_V[(b * NOBJ + j0 + j) * HID + t] = v[j] + vq;
    }
}

// ---------------- Kernel 1b: pack weights fp16, swizzled, k-major ------------
__global__ void prep_w_kernel(const float* __restrict__ w2, const float* __restrict__ w3,
                              const float* __restrict__ w4) {
    const int part = blockIdx.x, l = blockIdx.y;   // 8 parts x (k-half), layer
    const int h = part >> 2, sub = part & 3;
    const float* W = (l == 0) ? w2 : (l == 1) ? w3 : w4;
    __half* dst = g_Wpack + (size_t)(l * 2 + h) * 32768;
    const int base = sub * 8192;
    for (int i = threadIdx.x; i < 8192; i += 256) {
        int idx = base + i;
        int r = idx >> 8;     // local k row (0..127)
        int n = idx & 255;
        float w = W[(h * 128 + r) * HID + n];
        int phys = (r * 512 + ((n * 2) ^ ((r & 7) << 4))) >> 1;
        dst[phys] = __float2half_rn(w);
    }
}

// ---------------- Kernel 2: persistent HMMA fused pair MLP (grid=148) --------
// 256 threads, 8 warps, warp tile 64x64 (halves LDSM smem traffic vs 64x32).
static constexpr int SM_A     = 0;        // 64KB A fp16 [128x256] swizzled
static constexpr int SM_WBUF0 = 65536;    // 64KB
static constexpr int SM_WBUF1 = 131072;   // 64KB
static constexpr int SM_MBAR  = 196608;
static constexpr int SM_BIAS  = 196672;
static constexpr int SMEM_TOTAL = SM_BIAS + 3 * HID * 4;   // 199744 B

__global__ void __launch_bounds__(256, 1)
pair_mma_kernel(const float* __restrict__ b2, const float* __restrict__ b3,
                const float* __restrict__ b4) {
    extern __shared__ char smem[];
    const uint32_t sb = smem_u32(smem);

    const int tid = threadIdx.x;
    const int w = tid >> 5, lane = tid & 31;

    const int wm0 = (w & 1) * 64;        // warp M base (64 rows)
    const int wn0 = (w >> 1) * 64;       // warp N base (64 cols)

    const int lr = lane & 7;
    const int sxor = lr << 4;
    const int jr = (lane >> 3) & 1;
    const int jc = lane >> 4;

    const uint32_t fullb[2]  = {sb + SM_MBAR + 0,  sb + SM_MBAR + 8};
    const uint32_t emptyb[2] = {sb + SM_MBAR + 16, sb + SM_MBAR + 24};
    float* sbias = (float*)(smem + SM_BIAS);

    if (tid == 0) {
        MBAR_INIT(fullb[0], 1);    MBAR_INIT(fullb[1], 1);
        MBAR_INIT(emptyb[0], 256); MBAR_INIT(emptyb[1], 256);
    }
    sbias[tid] = b2[tid];
    sbias[HID + tid] = b3[tid];
    sbias[2 * HID + tid] = b4[tid];
    __syncthreads();

    const int ntiles = (NTILES - 1 - (int)blockIdx.x) / GRID_PAIR + 1;
    const int TOTAL = 6 * ntiles;

    if (tid == 0) {
        MBAR_EXPECT_TX(fullb[0], 65536u);
        bulk_g2s(sb + SM_WBUF0, g_Wpack, 65536u, fullb[0]);
        MBAR_EXPECT_TX(fullb[1], 65536u);
        bulk_g2s(sb + SM_WBUF1, g_Wpack + 32768, 65536u, fullb[1]);
    }
    int pf = 2;

    float acc[4][8][4];
#pragma unroll
    for (int mi = 0; mi < 4; mi++)
#pragma unroll
        for (int ni = 0; ni < 8; ni++)
#pragma unroll
            for (int r = 0; r < 4; r++) acc[mi][ni][r] = 0.f;

    uint32_t arow[4];
#pragma unroll
    for (int mi = 0; mi < 4; mi++)
        arow[mi] = sb + SM_A + (uint32_t)(wm0 + mi * 16 + 8 * jr + lr) * 512;
    const uint32_t browoff = (uint32_t)(8 * jr + lr) * 512;
    uint32_t cbp[4];
#pragma unroll
    for (int p = 0; p < 4; p++)
        cbp[p] = (uint32_t)(((wn0 + p * 16 + jc * 8) * 2) ^ sxor);

    int gctr = 0;
    for (int t = blockIdx.x; t < NTILES; t += GRID_PAIR) {
        const int q = t & 31, b = t >> 5;

        __syncthreads();   // previous tile's A reads complete

        // ---- A = h1 = relu(U[b,j] + V[b,a1]) as fp16, swizzled (float4) ----
        {
            const float* Ub = g_U + (size_t)b * NOBJ * HID;
            const float* V0 = g_V + ((size_t)b * NOBJ + 2 * q) * HID;
            for (int idx = tid; idx < 128 * 64; idx += 256) {
                int r = idx >> 6;
                int cq = (idx & 63) << 2;     // col base, multiple of 4
                int j = r & 63;
                const float* Vr = (r < 64) ? V0 : (V0 + HID);
                float4 uu = *(const float4*)(Ub + j * HID + cq);
                float4 vv = *(const float4*)(Vr + cq);
                __half2 h0 = __floats2half2_rn(fmaxf(uu.x + vv.x, 0.f),
                                               fmaxf(uu.y + vv.y, 0.f));
                __half2 h1 = __floats2half2_rn(fmaxf(uu.z + vv.z, 0.f),
                                               fmaxf(uu.w + vv.w, 0.f));
                int phys = r * 512 + ((2 * cq) ^ ((r & 7) << 4));  // 8B aligned, safe
                *(uint2*)(smem + SM_A + phys) = make_uint2(h2_bits(h0), h2_bits(h1));
            }
        }
        __syncthreads();

        for (int cl = 0; cl < 6; cl++, gctr++) {
            const int buf = gctr & 1;
            const int ph = (gctr >> 1) & 1;
            const uint32_t wb = sb + SM_WBUF0 + buf * 65536;
            mbar_wait(fullb[buf], ph);

#pragma unroll
            for (int ks = 0; ks < 8; ks++) {
                const int kg = (cl & 1) * 128 + ks * 16;
                const uint32_t acol = (uint32_t)((kg * 2 + jc * 16) ^ sxor);
                uint32_t af[4][4];
#pragma unroll
                for (int mi = 0; mi < 4; mi++)
                    LDSM_X4(af[mi][0], af[mi][1], af[mi][2], af[mi][3], arow[mi] + acol);
                uint32_t bh[4][4];
#pragma unroll
                for (int p = 0; p < 4; p++) {
                    uint32_t ba = wb + ks * 8192 + browoff + cbp[p];
                    LDSM_X4_T(bh[p][0], bh[p][1], bh[p][2], bh[p][3], ba);
                }
#pragma unroll
                for (int mi = 0; mi < 4; mi++)
#pragma unroll
                    for (int ni = 0; ni < 8; ni++)
                        mma16816(acc[mi][ni], af[mi], &bh[ni >> 1][(ni & 1) * 2]);
            }
            MBAR_ARRIVE(emptyb[buf]);
            if (tid == 0 && pf < TOTAL) {
                mbar_wait(emptyb[buf], ph);
                MBAR_EXPECT_TX(fullb[buf], 65536u);
                bulk_g2s(wb, g_Wpack + (size_t)(pf % 6) * 32768, 65536u, fullb[buf]);
                pf++;
            }

            if (cl == 1 || cl == 3) {
                const int layer = cl >> 1;
                __syncthreads();
                const float* bias = sbias + layer * HID;
#pragma unroll
                for (int mi = 0; mi < 4; mi++)
#pragma unroll
                    for (int ni = 0; ni < 8; ni++) {
                        const int col = wn0 + ni * 8 + 2 * (lane & 3);
                        const float b0v = bias[col], b1v = bias[col + 1];
                        const int r0 = wm0 + mi * 16 + (lane >> 2);
                        __half2 h01 = __floats2half2_rn(
                            fmaxf(acc[mi][ni][0] + b0v, 0.f),
                            fmaxf(acc[mi][ni][1] + b1v, 0.f));
                        __half2 h23 = __floats2half2_rn(
                            fmaxf(acc[mi][ni][2] + b0v, 0.f),
                            fmaxf(acc[mi][ni][3] + b1v, 0.f));
                        const int sw = (col * 2) ^ ((r0 & 7) << 4);
                        *(__half2*)(smem + SM_A + r0 * 512 + sw) = h01;
                        *(__half2*)(smem + SM_A + (r0 + 8) * 512 + sw) = h23;
#pragma unroll
                        for (int r = 0; r < 4; r++) acc[mi][ni][r] = 0.f;
                    }
                __syncthreads();
            } else if (cl == 5) {
                // final layer: relu+bias, warp-local column sums, direct STG
                const float* bias = sbias + 2 * HID;
                float colsum[8][2];
#pragma unroll
                for (int ni = 0; ni < 8; ni++)
#pragma unroll
                    for (int j = 0; j < 2; j++) {
                        const int col = wn0 + ni * 8 + 2 * (lane & 3) + j;
                        const float bv = bias[col];
                        float s = 0.f;
#pragma unroll
                        for (int mi = 0; mi < 4; mi++)
                            s += fmaxf(acc[mi][ni][j] + bv, 0.f) +
                                 fmaxf(acc[mi][ni][j + 2] + bv, 0.f);
                        s += __shfl_xor_sync(0xffffffffu, s, 4);
                        s += __shfl_xor_sync(0xffffffffu, s, 8);
                        s += __shfl_xor_sync(0xffffffffu, s, 16);
                        colsum[ni][j] = s;
                    }
                if (lane < 4) {
                    const int a1row = 2 * q + (w & 1);
                    float* dst = g_PART + ((size_t)b * NOBJ + a1row) * HID;
#pragma unroll
                    for (int ni = 0; ni < 8; ni++)
#pragma unroll
                        for (int j = 0; j < 2; j++)
                            dst[wn0 + ni * 8 + 2 * lane + j] = colsum[ni][j];
                }
#pragma unroll
                for (int mi = 0; mi < 4; mi++)
#pragma unroll
                    for (int ni = 0; ni < 8; ni++)
#pragma unroll
                        for (int r = 0; r < 4; r++) acc[mi][ni][r] = 0.f;
            }
        }
    }
}

// ---------------- Kernel 3: fused reduce + f MLP (k-split) + log_softmax -----
__global__ void reduce_f_kernel(const float* __restrict__ f1_w, const float* __restrict__ f1_b,
                                const float* __restrict__ f2_w, const float* __restrict__ f2_b,
                                const float* __restrict__ f3_w, const float* __restrict__ f3_b,
                                float* __restrict__ out) {
    __shared__ float red[1024];
    __shared__ float sa[HID];
    __shared__ float sb_[HID];
    __shared__ float sl[OUTC];
    __shared__ float lse;
    const int b = blockIdx.x, t = threadIdx.x;
    const int ch = t & 255, seg = t >> 8;
    const int c0 = seg * 64;

    // reduce PART over a1 (4-way)
    {
        const float* P = g_PART + (size_t)b * NOBJ * HID;
        float s = 0.f;
#pragma unroll
        for (int a1 = seg; a1 < NOBJ; a1 += 4) s += P[a1 * HID + ch];
        red[t] = s;
    }
    __syncthreads();
    if (t < 256) sa[t] = red[t] + red[t + 256] + red[t + 512] + red[t + 768];
    __syncthreads();

    // f1 (4-way k-split)
    {
        float acc = 0.f;
#pragma unroll 16
        for (int c = 0; c < 64; c++) acc += sa[c0 + c] * f1_w[(c0 + c) * HID + ch];
        red[t] = acc;
    }
    __syncthreads();
    if (t < 256) sb_[t] = fmaxf(red[t] + red[t + 256] + red[t + 512] + red[t + 768] + f1_b[t], 0.f);
    __syncthreads();

    // f2
    {
        float acc = 0.f;
#pragma unroll 16
        for (int c = 0; c < 64; c++) acc += sb_[c0 + c] * f2_w[(c0 + c) * HID + ch];
        red[t] = acc;
    }
    __syncthreads();
    if (t < 256) sa[t] = fmaxf(red[t] + red[t + 256] + red[t + 512] + red[t + 768] + f2_b[t], 0.f);
    __syncthreads();

    // f3
    if (t < 4 * OUTC) {
        const int o = t % OUTC, s3 = t / OUTC;
        float acc = 0.f;
#pragma unroll 16
        for (int c = 0; c < 64; c++) acc += sa[s3 * 64 + c] * f3_w[(s3 * 64 + c) * OUTC + o];
        red[t] = acc;
    }
    __syncthreads();
    if (t < OUTC)
        sl[t] = red[t] + red[t + OUTC] + red[t + 2 * OUTC] + red[t + 3 * OUTC] + f3_b[t];
    __syncthreads();

    if (t == 0) {
        float m = sl[0];
        for (int i = 1; i < OUTC; i++) m = fmaxf(m, sl[i]);
        float se = 0.0f;
        for (int i = 0; i < OUTC; i++) se += expf(sl[i] - m);
        lse = m + logf(se);
    }
    __syncthreads();
    if (t < OUTC) out[b * OUTC + t] = sl[t] - lse;
}

// ---------------------------------------------------------------------------
extern "C" void kernel_launch(void* const* d_in, const int* in_sizes, int n_in,
                              void* d_out, int out_size) {
    const float* x    = (const float*)d_in[0];
    const float* qst  = (const float*)d_in[1];
    const float* g1_w = (const float*)d_in[2];
    const float* g1_b = (const float*)d_in[3];
    const float* g2_w = (const float*)d_in[4];
    const float* g2_b = (const float*)d_in[5];
    const float* g3_w = (const float*)d_in[6];
    const float* g3_b = (const float*)d_in[7];
    const float* g4_w = (const float*)d_in[8];
    const float* g4_b = (const float*)d_in[9];
    const float* f1_w = (const float*)d_in[10];
    const float* f1_b = (const float*)d_in[11];
    const float* f2_w = (const float*)d_in[12];
    const float* f2_b = (const float*)d_in[13];
    const float* f3_w = (const float*)d_in[14];
    const float* f3_b = (const float*)d_in[15];
    float* out = (float*)d_out;

    cudaFuncSetAttribute(pair_mma_kernel, cudaFuncAttributeMaxDynamicSharedMemorySize,
                         SMEM_TOTAL);

    prep_w_kernel<<<dim3(8, 3), 256>>>(g2_w, g3_w, g4_w);
    prep_kernel<<<dim3(4, BATCH), 256>>>(x, qst, g1_w, g1_b);
    pair_mma_kernel<<<GRID_PAIR, 256, SMEM_TOTAL>>>(g2_b, g3_b, g4_b);
    reduce_f_kernel<<<BATCH, 1024>>>(f1_w, f1_b, f2_w, f2_b, f3_w, f3_b, out);
}

// round 14
// speedup vs baseline: 1.1643x; 1.1643x over previous
#include <cuda_runtime.h>
#include <cuda_fp16.h>
#include <cstdint>

#define BATCH 64
#define NOBJ  64
#define HID   256
#define OUTC  28
#define NTILES 2048
#define GRID_PAIR 148

__device__ float g_U[BATCH * NOBJ * HID];
__device__ float g_V[BATCH * NOBJ * HID];
__device__ float g_PART[BATCH * NOBJ * HID];
__device__ float g_XG[BATCH * HID];
// Packed weights (fp16): 6 chunks (3 layers x 2 k-halves), each 64KB
// = [128 k-rows x 256 n] fp16, swizzled: phys_byte = r*512 + ((n*2) ^ ((r&7)<<4))
__device__ __align__(128) __half g_Wpack[6 * 32768];

// ---------------- PTX helpers (sm_90-portable only) ----------------
__device__ __forceinline__ uint32_t smem_u32(const void* p) {
    uint32_t a;
    asm("{ .reg .u64 t; cvta.to.shared.u64 t, %1; cvt.u32.u64 %0, t; }" : "=r"(a) : "l"(p));
    return a;
}
#define MBAR_INIT(addr, cnt) \
    asm volatile("mbarrier.init.shared.b64 [%0], %1;" :: "r"(addr), "r"((uint32_t)(cnt)) : "memory")
#define MBAR_EXPECT_TX(addr, n) \
    asm volatile("mbarrier.arrive.expect_tx.shared.b64 _, [%0], %1;" :: "r"(addr), "r"((uint32_t)(n)) : "memory")
#define MBAR_ARRIVE(addr) \
    asm volatile("mbarrier.arrive.shared.b64 _, [%0];" :: "r"(addr) : "memory")

__device__ __forceinline__ void mbar_wait(uint32_t mbar, uint32_t parity) {
    asm volatile(
        "{\n\t.reg .pred P1;\n\t"
        "WL_%=:\n\t"
        "mbarrier.try_wait.parity.acquire.cta.shared::cta.b64 P1, [%0], %1, 0x989680;\n\t"
        "@P1 bra.uni WD_%=;\n\t"
        "bra.uni WL_%=;\n\t"
        "WD_%=:\n\t}"
        :: "r"(mbar), "r"(parity) : "memory");
}
__device__ __forceinline__ void bulk_g2s(uint32_t dst, const void* src,
                                         uint32_t bytes, uint32_t mbar) {
    asm volatile(
        "cp.async.bulk.shared::cluster.global.mbarrier::complete_tx::bytes [%0], [%1], %2, [%3];"
        :: "r"(dst), "l"(src), "r"(bytes), "r"(mbar) : "memory");
}

#define LDSM_X4(r0, r1, r2, r3, addr) \
    asm volatile("ldmatrix.sync.aligned.m8n8.x4.shared.b16 {%0,%1,%2,%3}, [%4];" \
                 : "=r"(r0), "=r"(r1), "=r"(r2), "=r"(r3) : "r"(addr))
#define LDSM_X4_T(r0, r1, r2, r3, addr) \
    asm volatile("ldmatrix.sync.aligned.m8n8.x4.trans.shared.b16 {%0,%1,%2,%3}, [%4];" \
                 : "=r"(r0), "=r"(r1), "=r"(r2), "=r"(r3) : "r"(addr))

__device__ __forceinline__ void mma16816(float* c, const uint32_t* a, const uint32_t* b) {
    asm volatile(
        "mma.sync.aligned.m16n8k16.row.col.f32.f16.f16.f32 "
        "{%0,%1,%2,%3}, {%4,%5,%6,%7}, {%8,%9}, {%0,%1,%2,%3};"
        : "+f"(c[0]), "+f"(c[1]), "+f"(c[2]), "+f"(c[3])
        : "r"(a[0]), "r"(a[1]), "r"(a[2]), "r"(a[3]), "r"(b[0]), "r"(b[1]));
}

// ---------------- Kernel 1: U, V (g1 split by linearity; qst hoisted) --------
__global__ void prep_kernel(const float* __restrict__ x, const float* __restrict__ qst,
                            const float* __restrict__ g1_w, const float* __restrict__ g1_b) {
    __shared__ float sxf[26][16];
    __shared__ float sq[128];
    const int b = blockIdx.y, j0 = blockIdx.x * 16, t = threadIdx.x;

    for (int i = t; i < 24 * 16; i += 256) {
        int k = i >> 4, j = i & 15;
        sxf[k][j] = x[(b * 24 + k) * 64 + j0 + j];
    }
    if (t < 16) sxf[24][t] = ((float)(j0 + t) * 0.125f - 4.0f) * 0.25f;
    else if (t < 32) {
        int j = t - 16;
        sxf[25][j] = ((float)((j0 + j) & 7) - 4.0f) * 0.25f;
    }
    if (t >= 128) sq[t - 128] = qst[b * 128 + (t - 128)];
    __syncthreads();

    float vq = g1_b[t];
#pragma unroll 8
    for (int q = 0; q < 128; q++) vq += sq[q] * g1_w[(52 + q) * HID + t];

    float u[16], v[16];
#pragma unroll
    for (int j = 0; j < 16; j++) { u[j] = 0.f; v[j] = 0.f; }
#pragma unroll
    for (int p = 0; p < 26; p++) {
        float wu = g1_w[p * HID + t];
        float wv = g1_w[(26 + p) * HID + t];
#pragma unroll
        for (int j = 0; j < 16; j++) {
            float s = sxf[p][j];
            u[j] += s * wu;
            v[j] += s * wv;
        }
    }
#pragma unroll
    for (int j = 0; j < 16; j++) {
        g_U[(b * NOBJ + j0 + j) * HID + t] = u[j];
        g_V[(b * NOBJ + j0 + j) * HID + t] = v[j] + vq;
    }
}

// ---------------- Kernel 1b: pack weights fp16, swizzled, k-major ------------
__global__ void prep_w_kernel(const float* __restrict__ w2, const float* __restrict__ w3,
                              const float* __restrict__ w4) {
    const int part = blockIdx.x, l = blockIdx.y;   // 8 parts x (k-half), layer
    const int h = part >> 2, sub = part & 3;
    const float* W = (l == 0) ? w2 : (l == 1) ? w3 : w4;
    __half* dst = g_Wpack + (size_t)(l * 2 + h) * 32768;
    const int base = sub * 8192;
    for (int i = threadIdx.x; i < 8192; i += 256) {
        int idx = base + i;
        int r = idx >> 8;     // local k row (0..127)
        int n = idx & 255;
        float w = W[(h * 128 + r) * HID + n];
        int phys = (r * 512 + ((n * 2) ^ ((r & 7) << 4))) >> 1;
        dst[phys] = __float2half_rn(w);
    }
}

// ---------------- Kernel 2: persistent HMMA fused pair MLP (grid=148) --------
// 512 threads, 16 warps, warp tile 64x32 (R8 proven config).
static constexpr int SM_A     = 0;        // 64KB A fp16 [128x256] swizzled
static constexpr int SM_WBUF0 = 65536;    // 64KB
static constexpr int SM_WBUF1 = 131072;   // 64KB
static constexpr int SM_MBAR  = 196608;
static constexpr int SM_BIAS  = 196672;
static constexpr int SMEM_TOTAL = SM_BIAS + 3 * HID * 4;   // 199744 B

__global__ void __launch_bounds__(512, 1)
pair_mma_kernel(const float* __restrict__ b2, const float* __restrict__ b3,
                const float* __restrict__ b4) {
    extern __shared__ char smem[];
    const uint32_t sb = smem_u32(smem);

    const int tid = threadIdx.x;
    const int w = tid >> 5, lane = tid & 31;

    const int wm0 = (w & 1) * 64;        // warp M base
    const int wn0 = (w >> 1) * 32;       // warp N base

    const int lr = lane & 7;
    const int sxor = lr << 4;
    const int jr = (lane >> 3) & 1;
    const int jc = lane >> 4;

    const uint32_t fullb[2]  = {sb + SM_MBAR + 0,  sb + SM_MBAR + 8};
    const uint32_t emptyb[2] = {sb + SM_MBAR + 16, sb + SM_MBAR + 24};
    float* sbias = (float*)(smem + SM_BIAS);

    if (tid == 0) {
        MBAR_INIT(fullb[0], 1);    MBAR_INIT(fullb[1], 1);
        MBAR_INIT(emptyb[0], 512); MBAR_INIT(emptyb[1], 512);
    }
    if (tid < 256) {
        sbias[tid] = b2[tid];
        sbias[HID + tid] = b3[tid];
        sbias[2 * HID + tid] = b4[tid];
    }
    __syncthreads();

    const int ntiles = (NTILES - 1 - (int)blockIdx.x) / GRID_PAIR + 1;
    const int TOTAL = 6 * ntiles;

    if (tid == 0) {
        MBAR_EXPECT_TX(fullb[0], 65536u);
        bulk_g2s(sb + SM_WBUF0, g_Wpack, 65536u, fullb[0]);
        MBAR_EXPECT_TX(fullb[1], 65536u);
        bulk_g2s(sb + SM_WBUF1, g_Wpack + 32768, 65536u, fullb[1]);
    }
    int pf = 2;

    float acc[4][4][4];
#pragma unroll
    for (int mi = 0; mi < 4; mi++)
#pragma unroll
        for (int ni = 0; ni < 4; ni++)
#pragma unroll
            for (int r = 0; r < 4; r++) acc[mi][ni][r] = 0.f;

    uint32_t arow[4];
#pragma unroll
    for (int mi = 0; mi < 4; mi++)
        arow[mi] = sb + SM_A + (uint32_t)(wm0 + mi * 16 + 8 * jr + lr) * 512;
    const uint32_t browoff = (uint32_t)(8 * jr + lr) * 512;
    uint32_t cbp[2];
#pragma unroll
    for (int p = 0; p < 2; p++)
        cbp[p] = (uint32_t)(((wn0 + p * 16 + jc * 8) * 2) ^ sxor);

    int gctr = 0;
    for (int t = blockIdx.x; t < NTILES; t += GRID_PAIR) {
        const int q = t & 31, b = t >> 5;

        __syncthreads();   // previous tile's A reads complete

        // ---- A = h1 = relu(U[b,j] + V[b,a1]) as fp16, swizzled ----
        {
            const float* Ub = g_U + (size_t)b * NOBJ * HID;
            const float* V0 = g_V + ((size_t)b * NOBJ + 2 * q) * HID;
            for (int idx = tid; idx < 128 * 128; idx += 512) {
                int r = idx >> 7;
                int p = idx & 127;
                int j = r & 63;
                const float* Vr = (r < 64) ? V0 : (V0 + HID);
                float2 uu = *(const float2*)(Ub + j * HID + 2 * p);
                float2 vv = *(const float2*)(Vr + 2 * p);
                __half2 h = __floats2half2_rn(fmaxf(uu.x + vv.x, 0.f),
                                              fmaxf(uu.y + vv.y, 0.f));
                int phys = r * 512 + ((4 * p) ^ ((r & 7) << 4));
                *(__half2*)(smem + SM_A + phys) = h;
            }
        }
        __syncthreads();

        for (int cl = 0; cl < 6; cl++, gctr++) {
            const int buf = gctr & 1;
            const int ph = (gctr >> 1) & 1;
            const uint32_t wb = sb + SM_WBUF0 + buf * 65536;
            mbar_wait(fullb[buf], ph);

#pragma unroll
            for (int ks = 0; ks < 8; ks++) {
                const int kg = (cl & 1) * 128 + ks * 16;
                const uint32_t acol = (uint32_t)((kg * 2 + jc * 16) ^ sxor);
                uint32_t af[4][4];
#pragma unroll
                for (int mi = 0; mi < 4; mi++)
                    LDSM_X4(af[mi][0], af[mi][1], af[mi][2], af[mi][3], arow[mi] + acol);
                uint32_t bh[2][4];
#pragma unroll
                for (int p = 0; p < 2; p++) {
                    uint32_t ba = wb + ks * 8192 + browoff + cbp[p];
                    LDSM_X4_T(bh[p][0], bh[p][1], bh[p][2], bh[p][3], ba);
                }
#pragma unroll
                for (int mi = 0; mi < 4; mi++)
#pragma unroll
                    for (int ni = 0; ni < 4; ni++)
                        mma16816(acc[mi][ni], af[mi], &bh[ni >> 1][(ni & 1) * 2]);
            }
            MBAR_ARRIVE(emptyb[buf]);
            if (tid == 0 && pf < TOTAL) {
                mbar_wait(emptyb[buf], ph);
                MBAR_EXPECT_TX(fullb[buf], 65536u);
                bulk_g2s(wb, g_Wpack + (size_t)(pf % 6) * 32768, 65536u, fullb[buf]);
                pf++;
            }

            if (cl == 1 || cl == 3) {
                const int layer = cl >> 1;
                __syncthreads();
                const float* bias = sbias + layer * HID;
#pragma unroll
                for (int mi = 0; mi < 4; mi++)
#pragma unroll
                    for (int ni = 0; ni < 4; ni++) {
                        const int col = wn0 + ni * 8 + 2 * (lane & 3);
                        const float b0v = bias[col], b1v = bias[col + 1];
                        const int r0 = wm0 + mi * 16 + (lane >> 2);
                        __half2 h01 = __floats2half2_rn(
                            fmaxf(acc[mi][ni][0] + b0v, 0.f),
                            fmaxf(acc[mi][ni][1] + b1v, 0.f));
                        __half2 h23 = __floats2half2_rn(
                            fmaxf(acc[mi][ni][2] + b0v, 0.f),
                            fmaxf(acc[mi][ni][3] + b1v, 0.f));
                        const int sw = (col * 2) ^ ((r0 & 7) << 4);
                        *(__half2*)(smem + SM_A + r0 * 512 + sw) = h01;
                        *(__half2*)(smem + SM_A + (r0 + 8) * 512 + sw) = h23;
#pragma unroll
                        for (int r = 0; r < 4; r++) acc[mi][ni][r] = 0.f;
                    }
                __syncthreads();
            } else if (cl == 5) {
                // final layer: relu+bias, warp-local column sums, float2 STG
                const float* bias = sbias + 2 * HID;
                float colsum[4][2];
#pragma unroll
                for (int ni = 0; ni < 4; ni++)
#pragma unroll
                    for (int j = 0; j < 2; j++) {
                        const int col = wn0 + ni * 8 + 2 * (lane & 3) + j;
                        const float bv = bias[col];
                        float s = 0.f;
#pragma unroll
                        for (int mi = 0; mi < 4; mi++)
                            s += fmaxf(acc[mi][ni][j] + bv, 0.f) +
                                 fmaxf(acc[mi][ni][j + 2] + bv, 0.f);
                        s += __shfl_xor_sync(0xffffffffu, s, 4);
                        s += __shfl_xor_sync(0xffffffffu, s, 8);
                        s += __shfl_xor_sync(0xffffffffu, s, 16);
                        colsum[ni][j] = s;
                    }
                if (lane < 4) {
                    const int a1row = 2 * q + (w & 1);
                    float* dst = g_PART + ((size_t)b * NOBJ + a1row) * HID;
#pragma unroll
                    for (int ni = 0; ni < 4; ni++)
                        *(float2*)(dst + wn0 + ni * 8 + 2 * lane) =
                            make_float2(colsum[ni][0], colsum[ni][1]);
                }
#pragma unroll
                for (int mi = 0; mi < 4; mi++)
#pragma unroll
                    for (int ni = 0; ni < 4; ni++)
#pragma unroll
                        for (int r = 0; r < 4; r++) acc[mi][ni][r] = 0.f;
            }
        }
    }
}

// ---------------- Kernel 3a: reduce g_PART over a1 -> g_XG (2 blocks/batch) --
__global__ void reduce_kernel() {
    __shared__ float red[1024];
    const int b = blockIdx.x >> 1, half = blockIdx.x & 1, t = threadIdx.x;
    const int ch = half * 128 + (t & 127), seg = t >> 7;   // 8 segments
    const float* P = g_PART + (size_t)b * NOBJ * HID;
    float s = 0.f;
#pragma unroll
    for (int a1 = seg; a1 < NOBJ; a1 += 8) s += P[a1 * HID + ch];
    red[t] = s;
    __syncthreads();
    if (t < 256) red[t] += red[t + 256] + red[t + 512] + red[t + 768];
    __syncthreads();
    if (t < 128)
        g_XG[b * HID + ch] = red[t] + red[t + 128];
}

// ---------------- Kernel 3b: f MLP + log_softmax (4-way k-split) -------------
__global__ void f_kernel(const float* __restrict__ f1_w, const float* __restrict__ f1_b,
                         const float* __restrict__ f2_w, const float* __restrict__ f2_b,
                         const float* __restrict__ f3_w, const float* __restrict__ f3_b,
                         float* __restrict__ out) {
    __shared__ float red[1024];
    __shared__ float sa[HID];
    __shared__ float sb_[HID];
    __shared__ float sl[OUTC];
    __shared__ float lse;
    const int b = blockIdx.x, t = threadIdx.x;
    const int ch = t & 255, seg = t >> 8;
    const int c0 = seg * 64;

    if (t < 256) sa[t] = g_XG[b * HID + t];
    __syncthreads();

    // f1 (4-way k-split)
    {
        float acc = 0.f;
#pragma unroll 16
        for (int c = 0; c < 64; c++) acc += sa[c0 + c] * f1_w[(c0 + c) * HID + ch];
        red[t] = acc;
    }
    __syncthreads();
    if (t < 256) sb_[t] = fmaxf(red[t] + red[t + 256] + red[t + 512] + red[t + 768] + f1_b[t], 0.f);
    __syncthreads();

    // f2
    {
        float acc = 0.f;
#pragma unroll 16
        for (int c = 0; c < 64; c++) acc += sb_[c0 + c] * f2_w[(c0 + c) * HID + ch];
        red[t] = acc;
    }
    __syncthreads();
    if (t < 256) sa[t] = fmaxf(red[t] + red[t + 256] + red[t + 512] + red[t + 768] + f2_b[t], 0.f);
    __syncthreads();

    // f3
    if (t < 4 * OUTC) {
        const int o = t % OUTC, s3 = t / OUTC;
        float acc = 0.f;
#pragma unroll 16
        for (int c = 0; c < 64; c++) acc += sa[s3 * 64 + c] * f3_w[(s3 * 64 + c) * OUTC + o];
        red[t] = acc;
    }
    __syncthreads();
    if (t < OUTC)
        sl[t] = red[t] + red[t + OUTC] + red[t + 2 * OUTC] + red[t + 3 * OUTC] + f3_b[t];
    __syncthreads();

    if (t == 0) {
        float m = sl[0];
        for (int i = 1; i < OUTC; i++) m = fmaxf(m, sl[i]);
        float se = 0.0f;
        for (int i = 0; i < OUTC; i++) se += expf(sl[i] - m);
        lse = m + logf(se);
    }
    __syncthreads();
    if (t < OUTC) out[b * OUTC + t] = sl[t] - lse;
}

// ---------------------------------------------------------------------------
extern "C" void kernel_launch(void* const* d_in, const int* in_sizes, int n_in,
                              void* d_out, int out_size) {
    const float* x    = (const float*)d_in[0];
    const float* qst  = (const float*)d_in[1];
    const float* g1_w = (const float*)d_in[2];
    const float* g1_b = (const float*)d_in[3];
    const float* g2_w = (const float*)d_in[4];
    const float* g2_b = (const float*)d_in[5];
    const float* g3_w = (const float*)d_in[6];
    const float* g3_b = (const float*)d_in[7];
    const float* g4_w = (const float*)d_in[8];
    const float* g4_b = (const float*)d_in[9];
    const float* f1_w = (const float*)d_in[10];
    const float* f1_b = (const float*)d_in[11];
    const float* f2_w = (const float*)d_in[12];
    const float* f2_b = (const float*)d_in[13];
    const float* f3_w = (const float*)d_in[14];
    const float* f3_b = (const float*)d_in[15];
    float* out = (float*)d_out;

    cudaFuncSetAttribute(pair_mma_kernel, cudaFuncAttributeMaxDynamicSharedMemorySize,
                         SMEM_TOTAL);

    prep_w_kernel<<<dim3(8, 3), 256>>>(g2_w, g3_w, g4_w);
    prep_kernel<<<dim3(4, BATCH), 256>>>(x, qst, g1_w, g1_b);
    pair_mma_kernel<<<GRID_PAIR, 512, SMEM_TOTAL>>>(g2_b, g3_b, g4_b);
    reduce_kernel<<<2 * BATCH, 1024>>>();
    f_kernel<<<BATCH, 1024>>>(f1_w, f1_b, f2_w, f2_b, f3_w, f3_b, out);
}